// round 9
// baseline (speedup 1.0000x reference)
#include <cuda_runtime.h>
#include <math.h>

// Shapes (hardcoded for this problem instance)
#define BB   2
#define HH   16
#define SS   2048
#define DD   128
#define MM   4096          // memories per head
#define QQ   4096          // B*S queries per head

#define TQ   128           // query tile per CTA
#define TM   64            // memory tile per iteration (double-buffered)
#define NTHREADS 256
#define SSTR 68            // sims row stride (divisible by 4 -> float4 aligned)

// Scratch: normalized queries and keys (32 MB each)
__device__ float g_qn[HH * QQ * DD];
__device__ float g_kn[HH * MM * DD];

// ---------------------------------------------------------------------------
// Normalization kernels: one warp per 128-float row
// ---------------------------------------------------------------------------
__global__ void norm_k_kernel(const float* __restrict__ km) {
    int wid  = (blockIdx.x * blockDim.x + threadIdx.x) >> 5;
    int lane = threadIdx.x & 31;
    if (wid >= HH * MM) return;
    float4 v = __ldg(((const float4*)(km + (size_t)wid * DD)) + lane);
    float ss = v.x * v.x + v.y * v.y + v.z * v.z + v.w * v.w;
    #pragma unroll
    for (int o = 16; o > 0; o >>= 1) ss += __shfl_xor_sync(0xffffffffu, ss, o);
    float inv = 1.0f / fmaxf(sqrtf(ss), 1e-11f);
    float4 r = make_float4(v.x * inv, v.y * inv, v.z * inv, v.w * inv);
    ((float4*)(g_kn + (size_t)wid * DD))[lane] = r;
}

__global__ void norm_q_kernel(const float* __restrict__ query) {
    int wid  = (blockIdx.x * blockDim.x + threadIdx.x) >> 5;
    int lane = threadIdx.x & 31;
    if (wid >= HH * QQ) return;
    int h = wid >> 12;          // / 4096
    int q = wid & (QQ - 1);
    int b = q >> 11;            // / 2048
    int s = q & (SS - 1);
    size_t src = ((size_t)((b * HH + h) * SS + s)) * DD;
    float4 v = __ldg(((const float4*)(query + src)) + lane);
    float ss = v.x * v.x + v.y * v.y + v.z * v.z + v.w * v.w;
    #pragma unroll
    for (int o = 16; o > 0; o >>= 1) ss += __shfl_xor_sync(0xffffffffu, ss, o);
    float inv = 1.0f / fmaxf(sqrtf(ss), 1e-11f);
    float4 r = make_float4(v.x * inv, v.y * inv, v.z * inv, v.w * inv);
    ((float4*)(g_qn + (size_t)wid * DD))[lane] = r;
}

// ---------------------------------------------------------------------------
// Q tile loader (one-time): 128x128 fp32 row-major -> SMEM transposed [d][q]
// swizzled: (row, d) -> dst[d*128 + ((row>>2)^((d>>2)&7))*4 + (row&3)]
// ---------------------------------------------------------------------------
__device__ __forceinline__ void load_q_tile(const float* __restrict__ src,
                                            float* __restrict__ dst, int tid) {
    const int w = tid >> 5;
    const int l = tid & 31;
    const int dbase = (w << 4) + ((l >> 3) << 2);
    #pragma unroll
    for (int i = 0; i < 16; ++i) {
        const int rl  = i & 3;
        const int row = ((i >> 2) << 5) + ((l & 7) << 2) + rl;
        float4 v = __ldg((const float4*)(src + (size_t)row * DD + dbase));
        float vv[4] = {v.x, v.y, v.z, v.w};
        const int cg = row >> 2;
        #pragma unroll
        for (int j = 0; j < 4; ++j) {
            const int d = dbase + j;
            dst[d * 128 + ((cg ^ ((d >> 2) & 7)) << 2) + rl] = vv[j];
        }
    }
}

// ---------------------------------------------------------------------------
// K tile (64 rows x 128 d): prefetch to regs, then store to SMEM transposed
// [d][m] (width 64) swizzled: (m, d) -> dst[d*64 + ((m>>2)^((d>>2)&15))*4 + (m&3)]
// Lane map gives ~4-way STS conflicts; LDG scatter is hidden by the GEMM overlap.
// ---------------------------------------------------------------------------
__device__ __forceinline__ void k_prefetch(const float* __restrict__ src,
                                           float4 pf[8], int tid) {
    const int w = tid >> 5;
    const int l = tid & 31;
    const int dbase = (w << 4) + ((l >> 3) << 2);
    #pragma unroll
    for (int i = 0; i < 8; ++i) {
        const int row = ((i >> 2) << 5) + ((l & 7) << 2) + (i & 3);  // 0..63
        pf[i] = __ldg((const float4*)(src + (size_t)row * DD + dbase));
    }
}

__device__ __forceinline__ void k_store(const float4 pf[8],
                                        float* __restrict__ dst, int tid) {
    const int w = tid >> 5;
    const int l = tid & 31;
    const int dbase = (w << 4) + ((l >> 3) << 2);
    #pragma unroll
    for (int i = 0; i < 8; ++i) {
        const int ml  = i & 3;
        const int row = ((i >> 2) << 5) + ((l & 7) << 2) + ml;
        const int mg  = row >> 2;
        float vv[4] = {pf[i].x, pf[i].y, pf[i].z, pf[i].w};
        #pragma unroll
        for (int j = 0; j < 4; ++j) {
            const int d = dbase + j;
            dst[d * 64 + ((mg ^ ((d >> 2) & 15)) << 2) + ml] = vv[j];
        }
    }
}

// Register-resident top-16 insert (static indices after unroll -> no spill)
__device__ __forceinline__ void insert16(float v, int idx,
                                         float tv[16], int ti[16],
                                         float& tmin, int& pmin) {
    #pragma unroll
    for (int j = 0; j < 16; ++j) {
        if (j == pmin) { tv[j] = v; ti[j] = idx; }
    }
    tmin = tv[0]; pmin = 0;
    #pragma unroll
    for (int j = 1; j < 16; ++j) {
        if (tv[j] < tmin) { tmin = tv[j]; pmin = j; }
    }
}

// ---------------------------------------------------------------------------
// Fused kernel: per (head, 128-query tile), 64 double-buffered 64-memory tiles:
//   store prefetched K -> sync -> prefetch next K -> GEMM (hides LDG) ->
//   stage sims -> sync -> selection.  Then merge, gather, blend, write.
// ---------------------------------------------------------------------------
__global__ void __launch_bounds__(NTHREADS, 1)
fused_knn_kernel(const float* __restrict__ vmem,
                 const float* __restrict__ outputs,
                 const float* __restrict__ gate,
                 float* __restrict__ out) {
    extern __shared__ float sm[];
    float* Qs = sm;                  // 16384 floats: Q tile [d][q] swizzled
    float* Kb0 = sm + 16384;         // 8192 floats: K tile buffer 0
    float* Kb1 = sm + 24576;         // 8192 floats: K tile buffer 1
    float* Ss  = sm + 32768;         // 128*SSTR floats: sims [q][m]

    const int h     = blockIdx.y;
    const int qbase = blockIdx.x * TQ;
    const int tid   = threadIdx.x;
    const int ty    = tid >> 4;      // 0..15 (query sub-rows: ty*8..ty*8+7)
    const int tx    = tid & 15;      // 0..15 (4 memory cols: tx*4..tx*4+3)
    const int srow  = tid >> 1;      // selection row 0..127
    const int spart = tid & 1;       // selection part (cols 0-31 / 32-63)

    load_q_tile(g_qn + ((size_t)(h * QQ + qbase)) * DD, Qs, tid);

    // top-16 state (registers)
    float tv[16]; int ti[16];
    #pragma unroll
    for (int j = 0; j < 16; ++j) { tv[j] = -1e30f; ti[j] = 0; }
    float tmin = -1e30f; int pmin = 0;

    const float* kh = g_kn + (size_t)h * MM * DD;

    float4 pf[8];
    k_prefetch(kh, pf, tid);         // tile 0

    for (int t = 0; t < MM / TM; ++t) {
        float* Kbuf = (t & 1) ? Kb1 : Kb0;
        k_store(pf, Kbuf, tid);
        __syncthreads();             // K tile visible; prev sims fully consumed

        if (t + 1 < MM / TM)
            k_prefetch(kh + (size_t)(t + 1) * TM * DD, pf, tid);

        float acc[8][4];
        #pragma unroll
        for (int i = 0; i < 8; ++i)
            #pragma unroll
            for (int j = 0; j < 4; ++j) acc[i][j] = 0.0f;

        #pragma unroll 4
        for (int kk = 0; kk < 128; ++kk) {
            const int s8  = (kk >> 2) & 7;
            const int s16 = (kk >> 2) & 15;
            const float4 a0 = *(const float4*)&Qs[kk * 128 + (((ty * 2)     ^ s8) << 2)];
            const float4 a1 = *(const float4*)&Qs[kk * 128 + (((ty * 2 + 1) ^ s8) << 2)];
            const float4 b  = *(const float4*)&Kbuf[kk * 64 + ((tx ^ s16) << 2)];
            const float a[8] = {a0.x, a0.y, a0.z, a0.w, a1.x, a1.y, a1.z, a1.w};
            #pragma unroll
            for (int i = 0; i < 8; ++i) {
                acc[i][0] += a[i] * b.x;
                acc[i][1] += a[i] * b.y;
                acc[i][2] += a[i] * b.z;
                acc[i][3] += a[i] * b.w;
            }
        }

        // stage sims: row ty*8+i, cols tx*4..+3 (STS.128, ~2-way)
        #pragma unroll
        for (int i = 0; i < 8; ++i)
            *(float4*)&Ss[(ty * 8 + i) * SSTR + tx * 4] =
                make_float4(acc[i][0], acc[i][1], acc[i][2], acc[i][3]);
        __syncthreads();

        // selection: thread (srow, spart) scans 32 candidates (float4)
        const float4* sp = (const float4*)(Ss + srow * SSTR + spart * 32);
        const int base = t * TM + spart * 32;
        #pragma unroll
        for (int c4 = 0; c4 < 8; ++c4) {
            float4 v = sp[c4];
            int bi = base + c4 * 4;
            if (v.x > tmin) insert16(v.x, bi + 0, tv, ti, tmin, pmin);
            if (v.y > tmin) insert16(v.y, bi + 1, tv, ti, tmin, pmin);
            if (v.z > tmin) insert16(v.z, bi + 2, tv, ti, tmin, pmin);
            if (v.w > tmin) insert16(v.w, bi + 3, tv, ti, tmin, pmin);
        }
    }

    // ---- merge the two part-top-16s per row ----
    __syncthreads();
    float* MV = Kb0;                      // 128*32 floats (16KB within Kb0/Kb1)
    int*   MI = (int*)(Kb0 + 4096);       // 128*32 ints
    {
        int mb = srow * 32 + spart * 16;
        #pragma unroll
        for (int j = 0; j < 16; ++j) { MV[mb + j] = tv[j]; MI[mb + j] = ti[j]; }
    }
    __syncthreads();

    float* FV = Qs;                       // 128*16 floats
    int*   FI = (int*)(Qs + 2048);        // 128*16 ints
    if (tid < 128) {
        #pragma unroll
        for (int j = 0; j < 16; ++j) { tv[j] = -1e30f; ti[j] = 0; }
        tmin = -1e30f; pmin = 0;
        #pragma unroll 2
        for (int c = 0; c < 32; ++c) {
            float v = MV[tid * 32 + c];
            if (v > tmin) insert16(v, MI[tid * 32 + c], tv, ti, tmin, pmin);
        }
        #pragma unroll
        for (int j = 0; j < 16; ++j) { FV[tid * 16 + j] = tv[j]; FI[tid * 16 + j] = ti[j]; }
    }
    __syncthreads();

    // ---- weighted value gather + gated blend ----
    const int row = tid >> 1;             // 0..127
    const int dh  = (tid & 1) << 6;       // 0 or 64
    float accd[64];
    #pragma unroll
    for (int u = 0; u < 64; ++u) accd[u] = 0.0f;

    const float* vh = vmem + (size_t)h * MM * DD;
    for (int j = 0; j < 16; ++j) {
        float sc = FV[row * 16 + j];
        int   ix = FI[row * 16 + j];
        const float4* vp = (const float4*)(vh + (size_t)ix * DD + dh);
        #pragma unroll
        for (int u = 0; u < 16; ++u) {
            float4 w = __ldg(vp + u);
            accd[4 * u + 0] += sc * w.x;
            accd[4 * u + 1] += sc * w.y;
            accd[4 * u + 2] += sc * w.z;
            accd[4 * u + 3] += sc * w.w;
        }
    }

    // Output flat index == wm flat index (raw reshape); gate head from out layout
    size_t l = ((size_t)(h * QQ + qbase + row)) * DD + dh;
    int hout = (int)((l >> 18) & (HH - 1));     // S*D = 2^18
    float gg = 1.0f / (1.0f + expf(-__ldg(gate + hout)));
    float og = 1.0f - gg;

    const float4* op = (const float4*)(outputs + l);
    float4*       wp = (float4*)(out + l);
    #pragma unroll
    for (int u = 0; u < 16; ++u) {
        float4 o = __ldg(op + u);
        float4 r;
        r.x = gg * accd[4 * u + 0] + og * o.x;
        r.y = gg * accd[4 * u + 1] + og * o.y;
        r.z = gg * accd[4 * u + 2] + og * o.z;
        r.w = gg * accd[4 * u + 3] + og * o.w;
        wp[u] = r;
    }
}

// ---------------------------------------------------------------------------
extern "C" void kernel_launch(void* const* d_in, const int* in_sizes, int n_in,
                              void* d_out, int out_size) {
    // metadata order: inputs, query, key, value, outputs, gate, key_memories, value_memories
    const float* query   = (const float*)d_in[1];
    const float* outputs = (const float*)d_in[4];
    const float* gate    = (const float*)d_in[5];
    const float* kmem    = (const float*)d_in[6];
    const float* vmem    = (const float*)d_in[7];
    float* out = (float*)d_out;

    const int smem_bytes = (32768 + 128 * SSTR) * (int)sizeof(float);  // 165888
    cudaFuncSetAttribute(fused_knn_kernel,
                         cudaFuncAttributeMaxDynamicSharedMemorySize, smem_bytes);

    norm_k_kernel<<<(HH * MM) / 8, 256>>>(kmem);
    norm_q_kernel<<<(HH * QQ) / 8, 256>>>(query);

    dim3 grid(QQ / TQ, HH);  // (32, 16)
    fused_knn_kernel<<<grid, NTHREADS, smem_bytes>>>(vmem, outputs, gate, out);
}

// round 10
// speedup vs baseline: 1.3844x; 1.3844x over previous
#include <cuda_runtime.h>
#include <math.h>

// Shapes (hardcoded for this problem instance)
#define BB   2
#define HH   16
#define SS   2048
#define DD   128
#define MM   4096          // memories per head
#define QQ   4096          // B*S queries per head

#define TQ   128           // query tile per CTA
#define TM   128           // memory tile per iteration
#define NTHREADS 512

// Scratch: normalized queries and keys (32 MB each)
__device__ float g_qn[HH * QQ * DD];
__device__ float g_kn[HH * MM * DD];

// ---------------------------------------------------------------------------
// Normalization kernels: one warp per 128-float row
// ---------------------------------------------------------------------------
__global__ void norm_k_kernel(const float* __restrict__ km) {
    int wid  = (blockIdx.x * blockDim.x + threadIdx.x) >> 5;
    int lane = threadIdx.x & 31;
    if (wid >= HH * MM) return;
    float4 v = __ldg(((const float4*)(km + (size_t)wid * DD)) + lane);
    float ss = v.x * v.x + v.y * v.y + v.z * v.z + v.w * v.w;
    #pragma unroll
    for (int o = 16; o > 0; o >>= 1) ss += __shfl_xor_sync(0xffffffffu, ss, o);
    float inv = 1.0f / fmaxf(sqrtf(ss), 1e-11f);
    float4 r = make_float4(v.x * inv, v.y * inv, v.z * inv, v.w * inv);
    ((float4*)(g_kn + (size_t)wid * DD))[lane] = r;
}

__global__ void norm_q_kernel(const float* __restrict__ query) {
    int wid  = (blockIdx.x * blockDim.x + threadIdx.x) >> 5;
    int lane = threadIdx.x & 31;
    if (wid >= HH * QQ) return;
    int h = wid >> 12;          // / 4096
    int q = wid & (QQ - 1);
    int b = q >> 11;            // / 2048
    int s = q & (SS - 1);
    size_t src = ((size_t)((b * HH + h) * SS + s)) * DD;
    float4 v = __ldg(((const float4*)(query + src)) + lane);
    float ss = v.x * v.x + v.y * v.y + v.z * v.z + v.w * v.w;
    #pragma unroll
    for (int o = 16; o > 0; o >>= 1) ss += __shfl_xor_sync(0xffffffffu, ss, o);
    float inv = 1.0f / fmaxf(sqrtf(ss), 1e-11f);
    float4 r = make_float4(v.x * inv, v.y * inv, v.z * inv, v.w * inv);
    ((float4*)(g_qn + (size_t)wid * DD))[lane] = r;
}

// ---------------------------------------------------------------------------
// Load a 128x128 fp32 tile (row-major [row][d]) into SMEM transposed [d][row]
// with XOR group-swizzle: element (row, d) -> dst[d*128 + ((row>>2)^((d>>2)&7))*4 + (row&3)]
// (R1 traversal, 512 threads: 8 float4 per thread)
// ---------------------------------------------------------------------------
__device__ __forceinline__ void load_tile_T(const float* __restrict__ src,
                                            float* __restrict__ dst, int tid) {
    #pragma unroll
    for (int i = 0; i < 8; ++i) {
        int f   = i * 512 + tid;        // float4 index 0..4095
        int row = f >> 5;               // 0..127
        int d0  = (f & 31) << 2;        // 0..124
        float4 v = __ldg((const float4*)(src + (size_t)row * DD + d0));
        float vv[4] = {v.x, v.y, v.z, v.w};
        int cg = row >> 2;
        int rl = row & 3;
        #pragma unroll
        for (int j = 0; j < 4; ++j) {
            int d = d0 + j;
            dst[d * 128 + (((cg) ^ ((d >> 2) & 7)) << 2) + rl] = vv[j];
        }
    }
}

// Register-resident top-16 insert (static indices after unroll -> no spill)
__device__ __forceinline__ void insert16(float v, int idx,
                                         float tv[16], int ti[16],
                                         float& tmin, int& pmin) {
    #pragma unroll
    for (int j = 0; j < 16; ++j) {
        if (j == pmin) { tv[j] = v; ti[j] = idx; }
    }
    tmin = tv[0]; pmin = 0;
    #pragma unroll
    for (int j = 1; j < 16; ++j) {
        if (tv[j] < tmin) { tmin = tv[j]; pmin = j; }
    }
}

// ---------------------------------------------------------------------------
// Fused kernel (R1 structure at 512 threads): per (head, 128-query tile):
//   loop over M in 128-chunks: SGEMM 128x128x128 -> SMEM sims -> top-16 update
//   then merge 4 parts/row, gather values, weighted sum, gated blend, write.
// Thread (ty, tx): ty=tid>>4 (0..31) owns rows ty*4..ty*4+3 (one swizzle group,
// so A is ONE float4); tx=tid&15 owns cols tx*8..tx*8+7 (two float4 groups).
// ---------------------------------------------------------------------------
__global__ void __launch_bounds__(NTHREADS, 1)
fused_knn_kernel(const float* __restrict__ vmem,
                 const float* __restrict__ outputs,
                 const float* __restrict__ gate,
                 float* __restrict__ out) {
    extern __shared__ float sm[];
    float* Qs = sm;                 // 16384 floats: Q tile [d][q] swizzled
    float* Ks = sm + 16384;         // 16384 floats: K tile [d][m] swizzled
    float* Ss = sm + 32768;         // 128*129 floats: sims [q][m] padded

    const int h     = blockIdx.y;
    const int qbase = blockIdx.x * TQ;
    const int tid   = threadIdx.x;
    const int ty    = tid >> 4;     // 0..31 (rows ty*4..ty*4+3)
    const int tx    = tid & 15;     // 0..15 (cols tx*8..tx*8+7)
    const int srow  = tid & 127;    // selection row
    const int spart = tid >> 7;     // selection part 0..3 (32 cols each)

    // Load and keep the Q tile resident
    load_tile_T(g_qn + ((size_t)(h * QQ + qbase)) * DD, Qs, tid);

    // top-16 state (registers)
    float tv[16]; int ti[16];
    #pragma unroll
    for (int j = 0; j < 16; ++j) { tv[j] = -1e30f; ti[j] = 0; }
    float tmin = -1e30f; int pmin = 0;

    const float* kh = g_kn + (size_t)h * MM * DD;

    for (int mt = 0; mt < MM; mt += TM) {
        __syncthreads();  // prev selection done with Ss; prev GEMM done with Ks
        load_tile_T(kh + (size_t)mt * DD, Ks, tid);
        __syncthreads();

        float acc[4][8];
        #pragma unroll
        for (int i = 0; i < 4; ++i)
            #pragma unroll
            for (int j = 0; j < 8; ++j) acc[i][j] = 0.0f;

        #pragma unroll 4
        for (int kk = 0; kk < 128; ++kk) {
            int s = (kk >> 2) & 7;
            const float4 a4 = *(const float4*)&Qs[kk * 128 + ((ty ^ s) << 2)];
            const float4 b0 = *(const float4*)&Ks[kk * 128 + (((tx * 2)     ^ s) << 2)];
            const float4 b1 = *(const float4*)&Ks[kk * 128 + (((tx * 2 + 1) ^ s) << 2)];
            float a[4] = {a4.x, a4.y, a4.z, a4.w};
            float b[8] = {b0.x, b0.y, b0.z, b0.w, b1.x, b1.y, b1.z, b1.w};
            #pragma unroll
            for (int i = 0; i < 4; ++i)
                #pragma unroll
                for (int j = 0; j < 8; ++j) acc[i][j] += a[i] * b[j];
        }

        // stage sims to shared (padded stride 129 -> conflict-free column scans)
        #pragma unroll
        for (int i = 0; i < 4; ++i)
            #pragma unroll
            for (int j = 0; j < 8; ++j)
                Ss[(ty * 4 + i) * 129 + tx * 8 + j] = acc[i][j];
        __syncthreads();

        // selection: thread (srow, spart) scans 32 candidates
        const float* sp = Ss + srow * 129 + spart * 32;
        const int base = mt + spart * 32;
        #pragma unroll 4
        for (int c = 0; c < 32; ++c) {
            float v = sp[c];
            if (v > tmin) insert16(v, base + c, tv, ti, tmin, pmin);
        }
    }

    // ---- merge the four parts per row ----
    __syncthreads();
    float* MV = Ks;                       // 128*64 floats (32KB)
    int*   MI = (int*)(Ks + 8192);        // 128*64 ints  (32KB)
    {
        int mb = srow * 64 + spart * 16;
        #pragma unroll
        for (int j = 0; j < 16; ++j) { MV[mb + j] = tv[j]; MI[mb + j] = ti[j]; }
    }
    __syncthreads();

    float* FV = Qs;                       // 128*16 floats
    int*   FI = (int*)(Qs + 2048);        // 128*16 ints
    if (tid < 128) {
        #pragma unroll
        for (int j = 0; j < 16; ++j) { tv[j] = -1e30f; ti[j] = 0; }
        tmin = -1e30f; pmin = 0;
        #pragma unroll 2
        for (int c = 0; c < 64; ++c) {
            float v = MV[tid * 64 + c];
            if (v > tmin) insert16(v, MI[tid * 64 + c], tv, ti, tmin, pmin);
        }
        #pragma unroll
        for (int j = 0; j < 16; ++j) { FV[tid * 16 + j] = tv[j]; FI[tid * 16 + j] = ti[j]; }
    }
    __syncthreads();

    // ---- weighted value gather + gated blend ----
    const int row = tid >> 2;             // 0..127
    const int dq  = (tid & 3) << 5;       // 0, 32, 64, 96
    float accd[32];
    #pragma unroll
    for (int u = 0; u < 32; ++u) accd[u] = 0.0f;

    const float* vh = vmem + (size_t)h * MM * DD;
    for (int j = 0; j < 16; ++j) {
        float sc = FV[row * 16 + j];
        int   ix = FI[row * 16 + j];
        const float4* vp = (const float4*)(vh + (size_t)ix * DD + dq);
        #pragma unroll
        for (int u = 0; u < 8; ++u) {
            float4 w = __ldg(vp + u);
            accd[4 * u + 0] += sc * w.x;
            accd[4 * u + 1] += sc * w.y;
            accd[4 * u + 2] += sc * w.z;
            accd[4 * u + 3] += sc * w.w;
        }
    }

    // Output flat index == wm flat index (raw reshape); gate head from out layout
    size_t l = ((size_t)(h * QQ + qbase + row)) * DD + dq;
    int hout = (int)((l >> 18) & (HH - 1));     // S*D = 2^18
    float gg = 1.0f / (1.0f + expf(-__ldg(gate + hout)));
    float og = 1.0f - gg;

    const float4* op = (const float4*)(outputs + l);
    float4*       wp = (float4*)(out + l);
    #pragma unroll
    for (int u = 0; u < 8; ++u) {
        float4 o = __ldg(op + u);
        float4 r;
        r.x = gg * accd[4 * u + 0] + og * o.x;
        r.y = gg * accd[4 * u + 1] + og * o.y;
        r.z = gg * accd[4 * u + 2] + og * o.z;
        r.w = gg * accd[4 * u + 3] + og * o.w;
        wp[u] = r;
    }
}

// ---------------------------------------------------------------------------
extern "C" void kernel_launch(void* const* d_in, const int* in_sizes, int n_in,
                              void* d_out, int out_size) {
    // metadata order: inputs, query, key, value, outputs, gate, key_memories, value_memories
    const float* query   = (const float*)d_in[1];
    const float* outputs = (const float*)d_in[4];
    const float* gate    = (const float*)d_in[5];
    const float* kmem    = (const float*)d_in[6];
    const float* vmem    = (const float*)d_in[7];
    float* out = (float*)d_out;

    const int smem_bytes = (32768 + 128 * 129) * (int)sizeof(float);  // 197120
    cudaFuncSetAttribute(fused_knn_kernel,
                         cudaFuncAttributeMaxDynamicSharedMemorySize, smem_bytes);

    norm_k_kernel<<<(HH * MM) / 8, 256>>>(kmem);
    norm_q_kernel<<<(HH * QQ) / 8, 256>>>(query);

    dim3 grid(QQ / TQ, HH);  // (32, 16)
    fused_knn_kernel<<<grid, NTHREADS, smem_bytes>>>(vmem, outputs, gate, out);
}